// round 1
// baseline (speedup 1.0000x reference)
#include <cuda_runtime.h>

#define N_NODES 50000
#define E_EDGES 800000
#define IN_DIM  128
#define OUT_DIM 64

// ---------------- scratch (device globals; allocation-free) ----------------
__device__ __align__(16) float    g_z[N_NODES * OUT_DIM];     // 12.8 MB
__device__ __align__(16) float    g_agg[N_NODES * OUT_DIM];   // 12.8 MB (unnormalized)
__device__ float    g_s1[N_NODES];
__device__ float    g_s2[N_NODES];
__device__ float    g_denom[N_NODES];
__device__ unsigned g_mx[N_NODES];                            // encoded float max keys
__device__ float    g_e[E_EDGES];                             // leaky-relu attention logits

// ============================================================================
// K1: z = h @ W_fc^T ; s1 = z.w1 ; s2 = z.w2 ; init agg/denom/mx
// One warp computes 4 full node rows (register tiling 2 outputs x 4 nodes).
// ============================================================================
__global__ void __launch_bounds__(128) k1_node(
    const float* __restrict__ h,
    const float* __restrict__ W,     // [64][128] row-major
    const float* __restrict__ attn)  // [192] = w1 | w2 | w3
{
    __shared__ __align__(16) float Wts[IN_DIM * 66];      // transposed, padded
    __shared__ __align__(16) float hw[4][IN_DIM][4];      // [warp][k][node-slot]

    const int tid = threadIdx.x;

    // transpose-load W: Wts[k*66 + j] = W[j*128 + k]
    for (int i = tid; i < OUT_DIM * IN_DIM; i += blockDim.x) {
        int j = i >> 7;        // i / 128
        int k = i & 127;       // i % 128
        Wts[k * 66 + j] = W[i];
    }
    __syncthreads();

    const int w = tid >> 5;
    const int l = tid & 31;

    const float2 w1 = ((const float2*)attn)[l];
    const float2 w2 = ((const float2*)(attn + OUT_DIM))[l];

    const int ntasks_stride = gridDim.x * 4;
    for (int task = blockIdx.x * 4 + w; task < N_NODES / 4; task += ntasks_stride) {
        const int node0 = task * 4;

        // stage 4 h rows into [k][m] layout (enables LDS.128 broadcast)
        #pragma unroll
        for (int m = 0; m < 4; m++) {
            const float* hp = h + (size_t)(node0 + m) * IN_DIM;
            #pragma unroll
            for (int t = 0; t < 4; t++)
                hw[w][t * 32 + l][m] = hp[t * 32 + l];
        }
        __syncwarp();

        float a0x = 0.f, a0y = 0.f, a0z = 0.f, a0w = 0.f;
        float a1x = 0.f, a1y = 0.f, a1z = 0.f, a1w = 0.f;
        #pragma unroll 16
        for (int k = 0; k < IN_DIM; k++) {
            const float4 hq = *(const float4*)&hw[w][k][0];
            const float2 wv = *(const float2*)&Wts[k * 66 + 2 * l];
            a0x += wv.x * hq.x; a0y += wv.x * hq.y; a0z += wv.x * hq.z; a0w += wv.x * hq.w;
            a1x += wv.y * hq.x; a1y += wv.y * hq.y; a1z += wv.y * hq.z; a1w += wv.y * hq.w;
        }
        __syncwarp();

        const float acc0[4] = {a0x, a0y, a0z, a0w};
        const float acc1[4] = {a1x, a1y, a1z, a1w};
        #pragma unroll
        for (int m = 0; m < 4; m++) {
            const int node = node0 + m;
            const float zx = acc0[m], zy = acc1[m];
            *(float2*)&g_z[(size_t)node * OUT_DIM + 2 * l]   = make_float2(zx, zy);
            *(float2*)&g_agg[(size_t)node * OUT_DIM + 2 * l] = make_float2(0.f, 0.f);
            float v1 = zx * w1.x + zy * w1.y;
            float v2 = zx * w2.x + zy * w2.y;
            #pragma unroll
            for (int off = 16; off; off >>= 1) {
                v1 += __shfl_xor_sync(0xffffffffu, v1, off);
                v2 += __shfl_xor_sync(0xffffffffu, v2, off);
            }
            if (l == 0) {
                g_s1[node] = v1;
                g_s2[node] = v2;
                g_denom[node] = 0.f;
                g_mx[node] = 0u;   // below any valid encoded float key
            }
        }
    }
}

// ============================================================================
// K2: per-edge logits + segment max. Half-warp (16 lanes) per edge.
// ============================================================================
__global__ void __launch_bounds__(256) k2_edge(
    const float* __restrict__ rh,
    const float* __restrict__ attn,
    const int* __restrict__ src,
    const int* __restrict__ dst)
{
    const int tid = blockIdx.x * blockDim.x + threadIdx.x;
    const int hw_id = tid >> 4;
    const int l = tid & 15;
    const int nhw = (gridDim.x * blockDim.x) >> 4;

    const float4 w3 = ((const float4*)(attn + 2 * OUT_DIM))[l];

    for (int e = hw_id; e < E_EDGES; e += nhw) {
        const float4 r = ((const float4*)(rh + (size_t)e * OUT_DIM))[l];
        float p = r.x * w3.x + r.y * w3.y + r.z * w3.z + r.w * w3.w;
        p += __shfl_xor_sync(0xffffffffu, p, 8);
        p += __shfl_xor_sync(0xffffffffu, p, 4);
        p += __shfl_xor_sync(0xffffffffu, p, 2);
        p += __shfl_xor_sync(0xffffffffu, p, 1);
        if (l == 0) {
            const int s = src[e];
            const int d = dst[e];
            const float a = g_s1[s] + g_s2[d] + p;
            const float ev = (a > 0.f) ? a : 0.01f * a;   // leaky relu
            g_e[e] = ev;
            const unsigned b = __float_as_uint(ev);
            const unsigned key = (b & 0x80000000u) ? ~b : (b | 0x80000000u);
            atomicMax(&g_mx[d], key);
        }
    }
}

// ============================================================================
// K3: e_exp = exp(e - max[dst]); denom += e_exp; agg[dst] += e_exp * z[src]
// Half-warp per edge; 64-float row scattered with red.global.add.v4.f32.
// ============================================================================
__global__ void __launch_bounds__(256) k3_scatter(
    const int* __restrict__ src,
    const int* __restrict__ dst)
{
    const int tid = blockIdx.x * blockDim.x + threadIdx.x;
    const int hw_id = tid >> 4;
    const int l = tid & 15;
    const int nhw = (gridDim.x * blockDim.x) >> 4;

    for (int e = hw_id; e < E_EDGES; e += nhw) {
        const int s = src[e];
        const int d = dst[e];
        const unsigned key = g_mx[d];
        const float m = __uint_as_float((key & 0x80000000u) ? (key ^ 0x80000000u) : ~key);
        const float ex = __expf(g_e[e] - m);
        if (l == 0) atomicAdd(&g_denom[d], ex);

        const float4 zq = *(const float4*)&g_z[(size_t)s * OUT_DIM + 4 * l];
        float* addr = &g_agg[(size_t)d * OUT_DIM + 4 * l];
        asm volatile("red.global.add.v4.f32 [%0], {%1, %2, %3, %4};"
                     :: "l"(addr), "f"(zq.x * ex), "f"(zq.y * ex),
                        "f"(zq.z * ex), "f"(zq.w * ex)
                     : "memory");
    }
}

// ============================================================================
// K4: out = relu( mask(denom>0) * (agg/denom + z @ loop_weight) )
// Same warp-per-4-nodes register tiling as K1 (loop_weight is already [k][j]).
// ============================================================================
__global__ void __launch_bounds__(128) k4_out(
    const float* __restrict__ LW,   // [64][64] row-major = [k][j]
    float* __restrict__ out)
{
    __shared__ __align__(16) float Ls[OUT_DIM * OUT_DIM];
    __shared__ __align__(16) float zw[4][OUT_DIM][4];

    const int tid = threadIdx.x;
    for (int i = tid; i < OUT_DIM * OUT_DIM; i += blockDim.x) Ls[i] = LW[i];
    __syncthreads();

    const int w = tid >> 5;
    const int l = tid & 31;
    const int ntasks_stride = gridDim.x * 4;

    for (int task = blockIdx.x * 4 + w; task < N_NODES / 4; task += ntasks_stride) {
        const int node0 = task * 4;

        #pragma unroll
        for (int m = 0; m < 4; m++) {
            const float* zp = g_z + (size_t)(node0 + m) * OUT_DIM;
            #pragma unroll
            for (int t = 0; t < 2; t++)
                zw[w][t * 32 + l][m] = zp[t * 32 + l];
        }
        __syncwarp();

        float a0x = 0.f, a0y = 0.f, a0z = 0.f, a0w = 0.f;
        float a1x = 0.f, a1y = 0.f, a1z = 0.f, a1w = 0.f;
        #pragma unroll 16
        for (int k = 0; k < OUT_DIM; k++) {
            const float4 zq = *(const float4*)&zw[w][k][0];
            const float2 lv = *(const float2*)&Ls[k * OUT_DIM + 2 * l];
            a0x += lv.x * zq.x; a0y += lv.x * zq.y; a0z += lv.x * zq.z; a0w += lv.x * zq.w;
            a1x += lv.y * zq.x; a1y += lv.y * zq.y; a1z += lv.y * zq.z; a1w += lv.y * zq.w;
        }
        __syncwarp();

        const float acc0[4] = {a0x, a0y, a0z, a0w};
        const float acc1[4] = {a1x, a1y, a1z, a1w};
        #pragma unroll
        for (int m = 0; m < 4; m++) {
            const int node = node0 + m;
            const float dn = g_denom[node];
            float2 o;
            if (dn > 0.f) {
                const float2 ag = *(const float2*)&g_agg[(size_t)node * OUT_DIM + 2 * l];
                const float inv = 1.0f / dn;
                o.x = fmaxf(ag.x * inv + acc0[m], 0.f);
                o.y = fmaxf(ag.y * inv + acc1[m], 0.f);
            } else {
                o.x = 0.f; o.y = 0.f;
            }
            *(float2*)&out[(size_t)node * OUT_DIM + 2 * l] = o;
        }
    }
}

// ============================================================================
// launch
// ============================================================================
extern "C" void kernel_launch(void* const* d_in, const int* in_sizes, int n_in,
                              void* d_out, int out_size)
{
    const float* h    = (const float*)d_in[0];
    const float* rh   = (const float*)d_in[1];
    const float* W    = (const float*)d_in[2];
    const float* attn = (const float*)d_in[3];
    const float* LW   = (const float*)d_in[4];
    const int*   src  = (const int*)d_in[5];
    const int*   dst  = (const int*)d_in[6];
    float* out = (float*)d_out;

    k1_node<<<1024, 128>>>(h, W, attn);
    k2_edge<<<1184, 256>>>(rh, attn, src, dst);
    k3_scatter<<<1184, 256>>>(src, dst);
    k4_out<<<1024, 128>>>(LW, out);
}